// round 16
// baseline (speedup 1.0000x reference)
#include <cuda_runtime.h>

// Problem constants (fixed by the reference)
#define BB   4
#define DD   512
#define NN   4096
#define HH   16      // heads
#define HD   32      // head dim
#define KK   9       // kernel taps
#define DIL  3
#define PADW 12      // DIL*(KK-1)/2
#define TILE 256
#define SPAN (TILE + 2 * PADW)   // 280, multiple of 4
#define NTHREADS 256

__global__ __launch_bounds__(NTHREADS, 3)
void dilattn_kernel(const float* __restrict__ q,
                    const float* __restrict__ k,
                    const float* __restrict__ v,
                    float* __restrict__ out) {
    extern __shared__ float smem[];
    float* kS = smem;                 // [HD][SPAN]
    float* vS = smem + HD * SPAN;     // [HD][SPAN]

    const int tid  = threadIdx.x;
    const int tile = blockIdx.x;
    const int h    = blockIdx.y;
    const int b    = blockIdx.z;
    const int n0   = tile * TILE;
    const int g0   = n0 - PADW;

    const size_t chan_base = ((size_t)b * DD + (size_t)h * HD) * NN;
    const float* kg = k + chan_base;
    const float* vg = v + chan_base;

    // ---- Stage k/v tiles (with zero-filled halo) into SMEM ----
    const bool interior = (g0 >= 0) && (g0 + SPAN <= NN);
    if (interior) {
        // vectorized float4 path: (n0-12)*4 bytes is 16B-aligned since n0 % 256 == 0
        const int NV = HD * (SPAN / 4);  // 2240 float4s per tensor
        #pragma unroll
        for (int it = 0; it < (NV + NTHREADS - 1) / NTHREADS; ++it) {
            int j = tid + it * NTHREADS;
            if (j < NV) {
                int c  = j / (SPAN / 4);
                int p4 = j - c * (SPAN / 4);
                const float4 kv = *(const float4*)(kg + (size_t)c * NN + g0 + p4 * 4);
                const float4 vv = *(const float4*)(vg + (size_t)c * NN + g0 + p4 * 4);
                *(float4*)(kS + c * SPAN + p4 * 4) = kv;
                *(float4*)(vS + c * SPAN + p4 * 4) = vv;
            }
        }
    } else {
        // boundary tiles: scalar guarded loads, zero outside [0, NN)
        for (int j = tid; j < HD * SPAN; j += NTHREADS) {
            int c = j / SPAN;
            int p = j - c * SPAN;
            int g = g0 + p;
            bool ok = (g >= 0) && (g < NN);
            kS[c * SPAN + p] = ok ? kg[(size_t)c * NN + g] : 0.0f;
            vS[c * SPAN + p] = ok ? vg[(size_t)c * NN + g] : 0.0f;
        }
    }
    __syncthreads();

    // ---- Logits: att[j] = sum_c q[c,n] * k[c, n + 3j - 12] (zero outside) ----
    float att[KK];
    #pragma unroll
    for (int j = 0; j < KK; ++j) att[j] = 0.0f;

    const float* qg = q + chan_base + (size_t)(n0 + tid);
    #pragma unroll
    for (int c = 0; c < HD; ++c) {
        float qc = __ldg(qg + (size_t)c * NN);
        #pragma unroll
        for (int j = 0; j < KK; ++j)
            att[j] += qc * kS[c * SPAN + tid + 3 * j];
    }

    // ---- Softmax over the 9 taps (scale folded into the exp arg) ----
    const float scale = 0.17677669529663687f;  // 32^-0.5
    float m = att[0];
    #pragma unroll
    for (int j = 1; j < KK; ++j) m = fmaxf(m, att[j]);
    float s = 0.0f;
    #pragma unroll
    for (int j = 0; j < KK; ++j) {
        att[j] = __expf((att[j] - m) * scale);
        s += att[j];
    }
    const float inv = 1.0f / s;
    #pragma unroll
    for (int j = 0; j < KK; ++j) att[j] *= inv;

    __syncthreads();  // all kS reads complete — safe to reuse kS as output stage

    // ---- Output: out[c] = sum_j att[j] * v[c, n + 3j - 12]; stage in SMEM ----
    float* outS = kS;  // [TILE][33] = 8448 floats <= 8960 (kS size); +1 pad kills bank conflicts
    #pragma unroll
    for (int c = 0; c < HD; ++c) {
        float acc = 0.0f;
        #pragma unroll
        for (int j = 0; j < KK; ++j)
            acc += att[j] * vS[c * SPAN + tid + 3 * j];
        outS[tid * 33 + c] = acc;
    }
    __syncthreads();

    // ---- Coalesced store: each warp writes one token's 32 channels = one 128B line ----
    float* og = out + ((size_t)b * NN + (size_t)n0) * DD + (size_t)h * HD;
    const int wid  = tid >> 5;
    const int lane = tid & 31;
    #pragma unroll
    for (int it = 0; it < TILE / 8; ++it) {
        int token = wid + it * 8;
        og[(size_t)token * DD + lane] = outS[token * 33 + lane];
    }
}

extern "C" void kernel_launch(void* const* d_in, const int* in_sizes, int n_in,
                              void* d_out, int out_size) {
    const float* q = (const float*)d_in[0];
    const float* k = (const float*)d_in[1];
    const float* v = (const float*)d_in[2];
    float* out = (float*)d_out;

    const size_t smem_bytes = (size_t)2 * HD * SPAN * sizeof(float);  // 71,680 B
    cudaFuncSetAttribute(dilattn_kernel,
                         cudaFuncAttributeMaxDynamicSharedMemorySize,
                         (int)smem_bytes);

    dim3 grid(NN / TILE, HH, BB);  // (16, 16, 4) = 1024 CTAs
    dilattn_kernel<<<grid, NTHREADS, smem_bytes>>>(q, k, v, out);
}